// round 7
// baseline (speedup 1.0000x reference)
#include <cuda_runtime.h>
#include <cstdint>

// Conv2d 3x3: x[32,128,56,56] f32 * w[256,128,3,3] f32 -> out[32,256,56,56]
// tf32 mma.sync implicit GEMM. CTA: M=256 oc x N=112 px (= exactly 2 image rows), K=1152.
// B: [k16][n112] smem stages filled by 16B cp.async from kw-shifted tf32 copies of x.
// A: fragment-packed tf32 in gmem, LDG.128 + register ping-pong.
// 8 warps (4M x 2N), warp tile M64xN56, 1 CTA/SM.

#define GUARD 64
#define NXF   12845056              // 32*128*56*56
#define XSTR  (NXF + 2*GUARD)
#define ROWW  120                   // words per k-row in B stage (112 + 8 pad)
#define STAGEB 7680                 // 16 * 120 * 4 bytes

__device__ float g_x3v[3 * (size_t)XSTR];     // kw-shifted tf32 copies of x
__device__ float g_prep[144 * 16 * 32 * 4];   // A fragments

static __device__ __forceinline__ uint32_t smem_u32(const void* p) {
    uint32_t a;
    asm("{ .reg .u64 t; cvta.to.shared.u64 t, %1; cvt.u32.u64 %0, t; }" : "=r"(a) : "l"(p));
    return a;
}
static __device__ __forceinline__ uint32_t totf(float f) {
    float r; asm("cvt.rna.tf32.f32 %0, %1;" : "=f"(r) : "f"(f));
    return __float_as_uint(r);
}

#define MMA1688(d, a, b0, b1) \
    asm volatile("mma.sync.aligned.m16n8k8.row.col.f32.tf32.tf32.f32 " \
        "{%0,%1,%2,%3}, {%4,%5,%6,%7}, {%8,%9}, {%0,%1,%2,%3};" \
        : "+f"((d)[0]), "+f"((d)[1]), "+f"((d)[2]), "+f"((d)[3]) \
        : "r"((a)[0]), "r"((a)[1]), "r"((a)[2]), "r"((a)[3]), "r"(b0), "r"(b1))

#define LDS32(r, addr) \
    asm volatile("ld.shared.b32 %0, [%1];" : "=r"(r) : "r"(addr))
#define STS32(addr, v) \
    asm volatile("st.shared.b32 [%0], %1;" :: "r"(addr), "r"(v) : "memory")

static __device__ __forceinline__ void cpa16(uint32_t dst, const float* src, int ok) {
    asm volatile(
        "{\n\t.reg .pred p;\n\t.reg .b32 sz;\n\t"
        "setp.ne.b32 p, %2, 0;\n\t"
        "selp.b32 sz, 16, 0, p;\n\t"
        "cp.async.ca.shared.global [%0], [%1], 16, sz;\n\t}"
        :: "r"(dst), "l"(src), "r"(ok) : "memory");
}
#define CP_COMMIT() asm volatile("cp.async.commit_group;" ::: "memory")
#define CP_WAIT2()  asm volatile("cp.async.wait_group 2;"  ::: "memory")

// ---- prep: A fragments [kb(144)][oc16(16)][lane(32)][4], tf32 bits ----
__global__ void __launch_bounds__(256)
prep_weights(const float* __restrict__ w) {
    int idx  = blockIdx.x * 256 + threadIdx.x;
    int j    = idx & 3;
    int lane = (idx >> 2) & 31;
    int oc16 = (idx >> 7) & 15;
    int kb   = idx >> 11;
    int row  = oc16 * 16 + (lane >> 2) + ((j & 1) ? 8 : 0);
    int col  = kb * 8 + (lane & 3) + ((j & 2) ? 4 : 0);
    g_prep[idx] = __uint_as_float(totf(w[(size_t)row * 1152 + col]));
}

// ---- prep: 3 kw-shifted tf32 copies of x: g_x3v[v][GUARD + i] = tf32(x[i + v - 1]) ----
__global__ void __launch_bounds__(256)
prep_x3(const float* __restrict__ x) {
    int gid = blockIdx.x * 256 + threadIdx.x;   // 0 .. 3211263
    int i0  = gid << 2;
    float4 v = *reinterpret_cast<const float4*>(x + i0);
    float rm = (i0 > 0) ? __ldg(x + i0 - 1) : 0.0f;
    float rp = (i0 + 4 < NXF) ? __ldg(x + i0 + 4) : 0.0f;
    float r[6];
    r[0] = __uint_as_float(totf(rm));
    r[1] = __uint_as_float(totf(v.x));
    r[2] = __uint_as_float(totf(v.y));
    r[3] = __uint_as_float(totf(v.z));
    r[4] = __uint_as_float(totf(v.w));
    r[5] = __uint_as_float(totf(rp));
    #pragma unroll
    for (int vv = 0; vv < 3; vv++) {
        float4 o = make_float4(r[vv], r[vv + 1], r[vv + 2], r[vv + 3]);
        *reinterpret_cast<float4*>(g_x3v + (size_t)vv * XSTR + GUARD + i0) = o;
    }
}

static __device__ __forceinline__ void stage_seg(
    const int* s_tbl, int ch, int kq, int a, uint32_t bS,
    const float* xb, bool top, bool bot)
{
    int e  = s_tbl[ch * 16 + kq];
    int kh = (e >> 2) & 3;
    const float* src = xb + (e >> 4) + 4 * a;
    int ok = 1;
    if (top && kh == 0 && a < 14)  ok = 0;
    if (bot && kh == 2 && a >= 14) ok = 0;
    cpa16(bS + (uint32_t)(((ch & 3) * STAGEB) + kq * 480 + a * 16), ok ? src : xb, ok);
}

static __device__ __forceinline__ void fix_seg(
    const int* s_tbl, int ch, int kq, int a, uint32_t bS)
{
    if (a != 0 && a != 13 && a != 14 && a != 27) return;
    int e  = s_tbl[ch * 16 + kq];
    int kw = e & 3;
    uint32_t rowb = bS + (uint32_t)(((ch & 3) * STAGEB) + kq * 480);
    if (kw == 0) {
        if (a == 0)  STS32(rowb, 0u);            // n = 0
        if (a == 14) STS32(rowb + 224, 0u);      // n = 56
    } else if (kw == 2) {
        if (a == 13) STS32(rowb + 220, 0u);      // n = 55
        if (a == 27) STS32(rowb + 444, 0u);      // n = 111
    }
}

__global__ void __launch_bounds__(256, 1)
conv3x3_tf32_hmma4(float* __restrict__ out)
{
    __shared__ int   s_tbl[1152];
    __shared__ float s_B[4 * 16 * ROWW];   // 30720 B

    const int tid   = threadIdx.x;
    const int lane  = tid & 31;
    const int wid   = tid >> 5;
    const int warpM = wid & 3;             // 64 oc each
    const int warpN = wid >> 2;            // 56 px each

    const int bx  = blockIdx.x;            // 0..27 row-pair
    const int img = blockIdx.y;
    const int p0  = bx * 112;
    const bool top = (bx == 0);
    const bool bot = (bx == 27);

    // k -> (kw*XSTR + ic*3136 + (kh-1)*56)<<4 | kh<<2 | kw
    for (int k = tid; k < 1152; k += 256) {
        int ic = k / 9;
        int r9 = k - ic * 9;
        int kh = r9 / 3;
        int kw = r9 - kh * 3;
        int t  = kw * XSTR + ic * 3136 + (kh - 1) * 56;
        s_tbl[k] = (t << 4) | (kh << 2) | kw;
    }

    // staging segments: 448 = 16 k-rows x 28 16B-segs; thread owns tid and tid+256
    const int kqA = tid / 28,  aA = tid - 28 * kqA;
    const bool hasB = (tid < 192);
    const int sB2 = tid + 256;
    const int kqB = sB2 / 28,  aB = sB2 - 28 * kqB;

    const float* xb = g_x3v + GUARD + (size_t)img * 401408 + p0;
    const uint32_t bS = smem_u32(s_B);

    // B fragment base: b0 = B[k = lane&3 (+8s)][n = warpN*56 + j*8 + lane>>2]
    const uint32_t bb = (uint32_t)((lane & 3) * ROWW + warpN * 56 + (lane >> 2)) * 4u;

    const float4* aP = reinterpret_cast<const float4*>(g_prep) + (size_t)(warpM * 4) * 32 + lane;

    float acc[4][7][4];
    #pragma unroll
    for (int i = 0; i < 4; i++)
        #pragma unroll
        for (int j = 0; j < 7; j++)
            #pragma unroll
            for (int q = 0; q < 4; q++) acc[i][j][q] = 0.0f;

    __syncthreads();   // table ready

    // prologue: stage chunks 0..2
    #pragma unroll
    for (int pre = 0; pre < 3; pre++) {
        stage_seg(s_tbl, pre, kqA, aA, bS, xb, top, bot);
        if (hasB) stage_seg(s_tbl, pre, kqB, aB, bS, xb, top, bot);
        CP_COMMIT();
    }

    // prologue: A regs for kb=0
    uint32_t af[2][4][4];
    #pragma unroll
    for (int i = 0; i < 4; i++) {
        float4 av = __ldg(aP + (size_t)i * 32);
        af[0][i][0] = __float_as_uint(av.x); af[0][i][1] = __float_as_uint(av.y);
        af[0][i][2] = __float_as_uint(av.z); af[0][i][3] = __float_as_uint(av.w);
    }

    #pragma unroll 1
    for (int ch = 0; ch < 72; ch++) {
        CP_WAIT2();
        // zero horizontally-wrapped pixels in own segments of stage ch
        fix_seg(s_tbl, ch, kqA, aA, bS);
        if (hasB) fix_seg(s_tbl, ch, kqB, aB, bS);
        __syncthreads();

        // stage chunk ch+3 (buffer (ch-1)&3, free after the barrier)
        if (ch + 3 < 72) {
            stage_seg(s_tbl, ch + 3, kqA, aA, bS, xb, top, bot);
            if (hasB) stage_seg(s_tbl, ch + 3, kqB, aB, bS, xb, top, bot);
        }
        CP_COMMIT();

        const uint32_t bBuf = bS + (uint32_t)((ch & 3) * STAGEB);
        #pragma unroll
        for (int s = 0; s < 2; s++) {
            const int kb  = ch * 2 + s;
            const int cur = kb & 1;
            if (kb + 1 < 144) {
                #pragma unroll
                for (int i = 0; i < 4; i++) {
                    float4 av = __ldg(aP + ((size_t)(kb + 1) * 16 + i) * 32);
                    af[cur ^ 1][i][0] = __float_as_uint(av.x);
                    af[cur ^ 1][i][1] = __float_as_uint(av.y);
                    af[cur ^ 1][i][2] = __float_as_uint(av.z);
                    af[cur ^ 1][i][3] = __float_as_uint(av.w);
                }
            }
            uint32_t b0[7], b1[7];
            const uint32_t ba = bBuf + (uint32_t)(s * 8 * ROWW * 4) + bb;
            #pragma unroll
            for (int j = 0; j < 7; j++) {
                LDS32(b0[j], ba + (uint32_t)(j * 32));
                LDS32(b1[j], ba + (uint32_t)(j * 32 + 4 * ROWW * 4));
            }
            #pragma unroll
            for (int i = 0; i < 4; i++)
                #pragma unroll
                for (int j = 0; j < 7; j++)
                    MMA1688(acc[i][j], af[cur][i], b0[j], b1[j]);
        }
    }

    // epilogue: STG.64 per fragment pair
    #pragma unroll
    for (int i = 0; i < 4; i++) {
        const int mrow = warpM * 64 + i * 16 + (lane >> 2);
        float* baseo = out + ((size_t)img * 256 + mrow) * 3136 + p0;
        #pragma unroll
        for (int j = 0; j < 7; j++) {
            int nl = warpN * 56 + j * 8 + 2 * (lane & 3);
            *reinterpret_cast<float2*>(baseo + nl)            = make_float2(acc[i][j][0], acc[i][j][1]);
            *reinterpret_cast<float2*>(baseo + 8 * 3136 + nl) = make_float2(acc[i][j][2], acc[i][j][3]);
        }
    }
}

extern "C" void kernel_launch(void* const* d_in, const int* in_sizes, int n_in,
                              void* d_out, int out_size) {
    const float* x = (const float*)d_in[0];   // [32,128,56,56]
    const float* w = (const float*)d_in[1];   // [256,128,3,3]
    float* out = (float*)d_out;               // [32,256,56,56]

    prep_weights<<<1152, 256>>>(w);
    prep_x3<<<12544, 256>>>(x);               // 3 shifted tf32 copies
    conv3x3_tf32_hmma4<<<dim3(28, 32), 256>>>(out);
}

// round 8
// speedup vs baseline: 1.4088x; 1.4088x over previous
#include <cuda_runtime.h>
#include <cstdint>

// Conv2d 3x3: x[32,128,56,56] f32 * w[256,128,3,3] f32 -> out[32,256,56,56]
// tf32 mma.sync implicit GEMM. CTA: M=256 oc x N=64 flat px, K=1152 (72 k16 chunks).
// A: fragment-packed tf32 in gmem, LDG.128 + register ping-pong (round-6 proven).
// B: [k16][n64] smem stages, 16B cp.async from kw-shifted tf32 copies, zfill verticals,
//    1-word STS fixes for horizontal wrap. 4-stage ring, 2 CTAs/SM.

#define GUARD 64
#define NXF   12845056              // 32*128*56*56
#define XSTR  (NXF + 2*GUARD)
#define ROWW2 72                    // words per k-row (64 + 8 pad)
#define STG   (16 * ROWW2 * 4)      // 4608 B per stage

__device__ float g_x3v[3 * (size_t)XSTR];     // kw-shifted tf32 copies of x
__device__ float g_prep[144 * 16 * 32 * 4];   // A fragments

static __device__ __forceinline__ uint32_t smem_u32(const void* p) {
    uint32_t a;
    asm("{ .reg .u64 t; cvta.to.shared.u64 t, %1; cvt.u32.u64 %0, t; }" : "=r"(a) : "l"(p));
    return a;
}
static __device__ __forceinline__ uint32_t totf(float f) {
    float r; asm("cvt.rna.tf32.f32 %0, %1;" : "=f"(r) : "f"(f));
    return __float_as_uint(r);
}

#define MMA1688(d, a, b0, b1) \
    asm volatile("mma.sync.aligned.m16n8k8.row.col.f32.tf32.tf32.f32 " \
        "{%0,%1,%2,%3}, {%4,%5,%6,%7}, {%8,%9}, {%0,%1,%2,%3};" \
        : "+f"((d)[0]), "+f"((d)[1]), "+f"((d)[2]), "+f"((d)[3]) \
        : "r"((a)[0]), "r"((a)[1]), "r"((a)[2]), "r"((a)[3]), "r"(b0), "r"(b1))

#define LDS32(r, addr) \
    asm volatile("ld.shared.b32 %0, [%1];" : "=r"(r) : "r"(addr))
#define STS32(addr, v) \
    asm volatile("st.shared.b32 [%0], %1;" :: "r"(addr), "r"(v) : "memory")

static __device__ __forceinline__ void cpa16(uint32_t dst, const float* src, int ok) {
    asm volatile(
        "{\n\t.reg .pred p;\n\t.reg .b32 sz;\n\t"
        "setp.ne.b32 p, %2, 0;\n\t"
        "selp.b32 sz, 16, 0, p;\n\t"
        "cp.async.ca.shared.global [%0], [%1], 16, sz;\n\t}"
        :: "r"(dst), "l"(src), "r"(ok) : "memory");
}
#define CP_COMMIT() asm volatile("cp.async.commit_group;" ::: "memory")
#define CP_WAIT2()  asm volatile("cp.async.wait_group 2;"  ::: "memory")

// ---- prep: A fragments [kb(144)][oc16(16)][lane(32)][4], tf32 bits ----
__global__ void __launch_bounds__(256)
prep_weights(const float* __restrict__ w) {
    int idx  = blockIdx.x * 256 + threadIdx.x;
    int j    = idx & 3;
    int lane = (idx >> 2) & 31;
    int oc16 = (idx >> 7) & 15;
    int kb   = idx >> 11;
    int row  = oc16 * 16 + (lane >> 2) + ((j & 1) ? 8 : 0);
    int col  = kb * 8 + (lane & 3) + ((j & 2) ? 4 : 0);
    g_prep[idx] = __uint_as_float(totf(w[(size_t)row * 1152 + col]));
}

// ---- prep: 3 kw-shifted tf32 copies: g_x3v[v][GUARD + i] = tf32(x[i + v - 1]) ----
__global__ void __launch_bounds__(256)
prep_x3(const float* __restrict__ x) {
    int gid = blockIdx.x * 256 + threadIdx.x;
    int i0  = gid << 2;
    float4 v = *reinterpret_cast<const float4*>(x + i0);
    float rm = (i0 > 0) ? __ldg(x + i0 - 1) : 0.0f;
    float rp = (i0 + 4 < NXF) ? __ldg(x + i0 + 4) : 0.0f;
    float r[6];
    r[0] = __uint_as_float(totf(rm));
    r[1] = __uint_as_float(totf(v.x));
    r[2] = __uint_as_float(totf(v.y));
    r[3] = __uint_as_float(totf(v.z));
    r[4] = __uint_as_float(totf(v.w));
    r[5] = __uint_as_float(totf(rp));
    #pragma unroll
    for (int vv = 0; vv < 3; vv++) {
        float4 o = make_float4(r[vv], r[vv + 1], r[vv + 2], r[vv + 3]);
        *reinterpret_cast<float4*>(g_x3v + (size_t)vv * XSTR + GUARD + i0) = o;
    }
}

__global__ void __launch_bounds__(256, 2)
conv3x3_tf32_hmma5(float* __restrict__ out)
{
    __shared__ int   s_tbl[1152];
    __shared__ float s_B[4 * 16 * ROWW2];   // 18432 B

    const int tid   = threadIdx.x;
    const int lane  = tid & 31;
    const int wid   = tid >> 5;
    const int warpM = wid & 3;              // 64 oc each
    const int warpN = wid >> 2;             // 32 px each

    const int img = blockIdx.x / 49;
    const int p0  = (blockIdx.x - img * 49) << 6;   // pixel offset within image

    // k -> (kw*XSTR + ic*3136 + (kh-1)*56)<<4 | kh<<2 | kw
    for (int k = tid; k < 1152; k += 256) {
        int ic = k / 9;
        int r9 = k - ic * 9;
        int kh = r9 / 3;
        int kw = r9 - kh * 3;
        int t  = kw * XSTR + ic * 3136 + (kh - 1) * 56;
        s_tbl[k] = (t << 4) | (kh << 2) | kw;
    }

    // ---- staging: thread owns one (k-row kq, 16B seg a) per chunk ----
    const int kq = tid >> 4;
    const int a  = tid & 15;
    const int pn   = p0 + 4 * a;       // first pixel of my segment
    const int rseg = pn / 56;          // image row (uniform across the segment)
    const int mseg = pn - rseg * 56;   // column of first pixel
    const float* xb = g_x3v + GUARD + (size_t)img * 401408 + p0;
    const uint32_t bS = smem_u32(s_B);
    const uint32_t my_dst = (uint32_t)(kq * (ROWW2 * 4) + a * 16);

    // ---- B fragment base (conflict-free LDS.32): word = (lane&3)*72 + warpN*32 + lane>>2 ----
    const uint32_t bb = (uint32_t)((lane & 3) * ROWW2 + warpN * 32 + (lane >> 2)) * 4u;

    const float4* aP = reinterpret_cast<const float4*>(g_prep) + (size_t)(warpM * 4) * 32 + lane;

    float acc[4][4][4];
    #pragma unroll
    for (int i = 0; i < 4; i++)
        #pragma unroll
        for (int j = 0; j < 4; j++)
            #pragma unroll
            for (int q = 0; q < 4; q++) acc[i][j][q] = 0.0f;

    __syncthreads();   // table ready

    // ---- prologue: stage chunks 0..2 ----
    #pragma unroll
    for (int pre = 0; pre < 3; pre++) {
        int e  = s_tbl[pre * 16 + kq];
        int kh = (e >> 2) & 3;
        int ok = (unsigned)(rseg + kh - 1) < 56u;
        cpa16(bS + (uint32_t)(pre * STG) + my_dst, ok ? (xb + (e >> 4) + 4 * a) : xb, ok);
        CP_COMMIT();
    }

    // ---- prologue: A regs for kb=0 ----
    uint32_t af[2][4][4];
    #pragma unroll
    for (int i = 0; i < 4; i++) {
        float4 av = __ldg(aP + (size_t)i * 32);
        af[0][i][0] = __float_as_uint(av.x); af[0][i][1] = __float_as_uint(av.y);
        af[0][i][2] = __float_as_uint(av.z); af[0][i][3] = __float_as_uint(av.w);
    }

    #pragma unroll 1
    for (int ch = 0; ch < 72; ch++) {
        CP_WAIT2();
        // horizontal-wrap fixes in my segment of stage ch (first/last word only)
        {
            int e  = s_tbl[ch * 16 + kq];
            int kw = e & 3;
            uint32_t rb = bS + (uint32_t)((ch & 3) * STG) + my_dst;
            if (kw == 0 && mseg == 0)  STS32(rb, 0u);        // c == 0
            if (kw == 2 && mseg == 52) STS32(rb + 12, 0u);   // c == 55 (last word)
        }
        __syncthreads();

        // stage chunk ch+3 (its buffer was consumed in iteration ch-1)
        if (ch + 3 < 72) {
            int e  = s_tbl[(ch + 3) * 16 + kq];
            int kh = (e >> 2) & 3;
            int ok = (unsigned)(rseg + kh - 1) < 56u;
            cpa16(bS + (uint32_t)(((ch + 3) & 3) * STG) + my_dst,
                  ok ? (xb + (e >> 4) + 4 * a) : xb, ok);
        }
        CP_COMMIT();

        const uint32_t bBuf = bS + (uint32_t)((ch & 3) * STG);
        #pragma unroll
        for (int s = 0; s < 2; s++) {
            const int kb  = ch * 2 + s;
            const int cur = kb & 1;
            if (kb + 1 < 144) {
                #pragma unroll
                for (int i = 0; i < 4; i++) {
                    float4 av = __ldg(aP + ((size_t)(kb + 1) * 16 + i) * 32);
                    af[cur ^ 1][i][0] = __float_as_uint(av.x);
                    af[cur ^ 1][i][1] = __float_as_uint(av.y);
                    af[cur ^ 1][i][2] = __float_as_uint(av.z);
                    af[cur ^ 1][i][3] = __float_as_uint(av.w);
                }
            }
            // B fragments: k-rows s*8 + (lane&3) (+4 for b1), n = warpN*32 + j*8 + lane>>2
            const uint32_t ba = bBuf + (uint32_t)(s * 8 * ROWW2 * 4) + bb;
            uint32_t b0[4], b1[4];
            #pragma unroll
            for (int j = 0; j < 4; j++) {
                LDS32(b0[j], ba + (uint32_t)(j * 32));
                LDS32(b1[j], ba + (uint32_t)(j * 32 + 4 * ROWW2 * 4));
            }
            #pragma unroll
            for (int i = 0; i < 4; i++)
                #pragma unroll
                for (int j = 0; j < 4; j++)
                    MMA1688(acc[i][j], af[cur][i], b0[j], b1[j]);
        }
    }

    // ---- epilogue: STG.64 per fragment pair ----
    const int gp0 = blockIdx.x << 6;
    #pragma unroll
    for (int i = 0; i < 4; i++) {
        const int mrow = warpM * 64 + i * 16 + (lane >> 2);
        #pragma unroll
        for (int j = 0; j < 4; j++) {
            int nl  = warpN * 32 + j * 8 + 2 * (lane & 3);
            int gp2 = gp0 + nl;
            int im2 = gp2 / 3136;
            int pp  = gp2 - im2 * 3136;
            float* o0 = out + ((size_t)im2 * 256 + mrow) * 3136 + pp;
            *reinterpret_cast<float2*>(o0)            = make_float2(acc[i][j][0], acc[i][j][1]);
            *reinterpret_cast<float2*>(o0 + 8 * 3136) = make_float2(acc[i][j][2], acc[i][j][3]);
        }
    }
}

extern "C" void kernel_launch(void* const* d_in, const int* in_sizes, int n_in,
                              void* d_out, int out_size) {
    const float* x = (const float*)d_in[0];   // [32,128,56,56]
    const float* w = (const float*)d_in[1];   // [256,128,3,3]
    float* out = (float*)d_out;               // [32,256,56,56]

    prep_weights<<<1152, 256>>>(w);
    prep_x3<<<12544, 256>>>(x);               // 3 shifted tf32 copies
    conv3x3_tf32_hmma5<<<1568, 256>>>(out);
}